// round 4
// baseline (speedup 1.0000x reference)
#include <cuda_runtime.h>
#include <cstddef>

#define LCH   4096
#define BATCH 4096
#define SEG   32
#define NSEG  128

struct Pots { float pd, po, pA0, pA1, pB0, pB1; };

__device__ __forceinline__ Pots make_pots(const float* jp, const float* bp) {
    Pots P;
    float j = jp[0], b0 = bp[0], b1 = bp[1];
    P.pd  = expf( 0.25f * j);
    P.po  = expf(-0.25f * j);
    P.pA0 = expf(-0.5f * b0);  P.pA1 = expf(0.5f * b0);
    P.pB0 = expf(-0.5f * b1);  P.pB1 = expf(0.5f * b1);
    return P;
}

// (max,*) 2x2 matrix product: C = A x B.  layout x=m00 y=m01 z=m10 w=m11
__device__ __forceinline__ float4 mm(float4 A, float4 B) {
    return make_float4(
        fmaxf(A.x * B.x, A.y * B.z), fmaxf(A.x * B.y, A.y * B.w),
        fmaxf(A.z * B.x, A.w * B.z), fmaxf(A.z * B.y, A.w * B.w));
}

__device__ __forceinline__ float4 shflup4(float4 v, int d) {
    v.x = __shfl_up_sync(0xffffffffu, v.x, d);
    v.y = __shfl_up_sync(0xffffffffu, v.y, d);
    v.z = __shfl_up_sync(0xffffffffu, v.z, d);
    v.w = __shfl_up_sync(0xffffffffu, v.w, d);
    return v;
}
__device__ __forceinline__ float4 shfldn4(float4 v, int d) {
    v.x = __shfl_down_sync(0xffffffffu, v.x, d);
    v.y = __shfl_down_sync(0xffffffffu, v.y, d);
    v.z = __shfl_down_sync(0xffffffffu, v.z, d);
    v.w = __shfl_down_sync(0xffffffffu, v.w, d);
    return v;
}

// ---------------------------------------------------------------------------
// One block per row. Segment transfer matrices -> block (max,*) matrix scan
// -> checkpointed backward sweep -> forward belief sweep -> coalesced store.
// ---------------------------------------------------------------------------
__global__ void __launch_bounds__(128, 6)
fused(const float* __restrict__ jp, const float* __restrict__ bp,
      const int* __restrict__ obs, float* __restrict__ out)
{
    const int t = threadIdx.x, b = blockIdx.x;
    const int lane = t & 31, warp = t >> 5;

    __shared__ unsigned char smNib[1024];
    __shared__ float4 lutP[16], lutQ[16];
    __shared__ float4 wTotP[4], wTotQ[4];
    __shared__ float  smo[2 * LCH];         // 32 KB output stage
    float4* sm4 = reinterpret_cast<float4*>(smo);

    const Pots pt = make_pots(jp, bp);

    // ---- obs -> nibbles (coalesced int4 loads) ----
    const int4* row4 = reinterpret_cast<const int4*>(obs + (size_t)b * LCH);
#pragma unroll
    for (int q = 0; q < 8; q++) {
        int  eq = q * 128 + t;
        int4 v  = __ldcs(row4 + eq);
        unsigned nib = (v.x & 1) | ((v.y & 1) << 1) | ((v.z & 1) << 2) | ((v.w & 1) << 3);
        smNib[eq] = (unsigned char)nib;
    }

    // ---- 4-bit LUTs of 4-step transfer matrices ----
    if (t < 16) {
        float p00 = 1.f, p01 = 0.f, p10 = 0.f, p11 = 1.f;
        float q00 = 1.f, q01 = 0.f, q10 = 0.f, q11 = 1.f;
#pragma unroll
        for (int i = 0; i < 4; i++) {
            int   o  = (t >> i) & 1;
            float f0 = o ? pt.pB0 : pt.pA0;
            float f1 = o ? pt.pB1 : pt.pA1;
            float x0 = f0 * p00, x1 = f1 * p10, y0 = f0 * p01, y1 = f1 * p11;
            p00 = fmaxf(x0 * pt.pd, x1 * pt.po); p10 = fmaxf(x0 * pt.po, x1 * pt.pd);
            p01 = fmaxf(y0 * pt.pd, y1 * pt.po); p11 = fmaxf(y0 * pt.po, y1 * pt.pd);
            float a = f0 * fmaxf(q00 * pt.pd, q01 * pt.po);
            float c = f1 * fmaxf(q00 * pt.po, q01 * pt.pd);
            float d = f0 * fmaxf(q10 * pt.pd, q11 * pt.po);
            float e = f1 * fmaxf(q10 * pt.po, q11 * pt.pd);
            q00 = a; q01 = c; q10 = d; q11 = e;
        }
        lutP[t] = make_float4(p00, p01, p10, p11);
        lutQ[t] = make_float4(q00, q01, q10, q11);
    }
    __syncthreads();

    // ---- assemble 32-bit mask for segment t ----
    uint2 nb = reinterpret_cast<const uint2*>(smNib)[t];
    unsigned lo   = nb.x | (nb.x >> 4);
    unsigned lo16 = (lo & 0xFFu) | ((lo >> 8) & 0xFF00u);
    unsigned hi   = nb.y | (nb.y >> 4);
    unsigned hi16 = (hi & 0xFFu) | ((hi >> 8) & 0xFF00u);
    const unsigned bits = lo16 | (hi16 << 16);

    // ---- segment transfer matrices via LUT chains ----
    float4 P = lutP[bits & 15];
    float4 Q = lutQ[bits & 15];
#pragma unroll
    for (int c = 1; c < 8; c++) {
        unsigned m = (bits >> (4 * c)) & 15u;
        P = mm(lutP[m], P);
        Q = mm(Q, lutQ[m]);
    }

    // ---- block scan: forward prefix of P, backward suffix of Q ----
    float4 sp = P;
#pragma unroll
    for (int d = 1; d < 32; d <<= 1) {
        float4 o = shflup4(sp, d);
        if (lane >= d) sp = mm(sp, o);
    }
    if (lane == 31) wTotP[warp] = sp;

    float4 sq = Q;
#pragma unroll
    for (int d = 1; d < 32; d <<= 1) {
        float4 o = shfldn4(sq, d);
        if (lane + d < 32) sq = mm(sq, o);
    }
    if (lane == 0) wTotQ[warp] = sq;
    __syncthreads();

    float4 prefP = make_float4(1.f, 0.f, 0.f, 1.f);
#pragma unroll
    for (int k = 2; k >= 0; k--)
        if (warp > k) prefP = mm(prefP, wTotP[k]);

    float4 sufQ = make_float4(1.f, 0.f, 0.f, 1.f);
#pragma unroll
    for (int k = 1; k < 4; k++)
        if (warp < k) sufQ = mm(sufQ, wTotQ[k]);

    float4 exP = shflup4(sp, 1);
    if (lane == 0) exP = make_float4(1.f, 0.f, 0.f, 1.f);
    exP = mm(exP, prefP);
    float f0 = fmaxf(exP.x, exP.y), f1 = fmaxf(exP.z, exP.w);  // fwd msg at seg start

    float4 exQ = shfldn4(sq, 1);
    if (lane == 31) exQ = make_float4(1.f, 0.f, 0.f, 1.f);
    exQ = mm(exQ, sufQ);
    float g0 = fmaxf(exQ.x, exQ.y), g1 = fmaxf(exQ.z, exQ.w);  // bwd msg at seg end

    // ---- backward checkpoint sweep: keep b at each group-of-4 end ----
    float c0[8], c1[8];
    {
        float bk0 = g0, bk1 = g1;          // b at position 31
#pragma unroll
        for (int gg = 7; gg >= 0; gg--) {
            c0[gg] = bk0; c1[gg] = bk1;    // b at position gg*4+3
#pragma unroll
            for (int u = 3; u >= 0; u--) {
                int   i  = gg * 4 + u;
                int   o  = (bits >> i) & 1;
                float p0 = o ? pt.pB0 : pt.pA0;
                float p1 = o ? pt.pB1 : pt.pA1;
                float y0 = p0 * bk0, y1 = p1 * bk1;
                bk0 = fmaxf(y0 * pt.pd, y1 * pt.po);
                bk1 = fmaxf(y0 * pt.po, y1 * pt.pd);
            }
        }
    }

    // ---- forward belief sweep (recompute b within each group) ----
    const int xr = t & 7;
#pragma unroll
    for (int gg = 0; gg < 8; gg++) {
        // recover backward msgs inside the group from checkpoint at its end
        float b0[4], b1[4];
        b0[3] = c0[gg]; b1[3] = c1[gg];
#pragma unroll
        for (int u = 3; u >= 1; u--) {
            int   i  = gg * 4 + u;
            int   o  = (bits >> i) & 1;
            float p0 = o ? pt.pB0 : pt.pA0;
            float p1 = o ? pt.pB1 : pt.pA1;
            float y0 = p0 * b0[u], y1 = p1 * b1[u];
            b0[u - 1] = fmaxf(y0 * pt.pd, y1 * pt.po);
            b1[u - 1] = fmaxf(y0 * pt.po, y1 * pt.pd);
        }
        float v0[4], v1[4];
#pragma unroll
        for (int u = 0; u < 4; u++) {
            int   i  = gg * 4 + u;
            int   o  = (bits >> i) & 1;
            float p0 = o ? pt.pB0 : pt.pA0;
            float p1 = o ? pt.pB1 : pt.pA1;
            float x0 = p0 * f0, x1 = p1 * f1;
            v0[u] = x0 * b0[u];
            v1[u] = x1 * b1[u];
            f0 = fmaxf(x0 * pt.pd, x1 * pt.po);
            f1 = fmaxf(x0 * pt.po, x1 * pt.pd);
        }
        sm4[(t * 8 + gg) ^ xr]        = make_float4(v0[0], v0[1], v0[2], v0[3]);
        sm4[(1024 + t * 8 + gg) ^ xr] = make_float4(v1[0], v1[1], v1[2], v1[3]);
    }
    __syncthreads();

    // ---- cooperative fully-coalesced streaming store: out[b][k][t] ----
    float4* out4 = reinterpret_cast<float4*>(out) + (size_t)b * 2048;
#pragma unroll
    for (int r = 0; r < 16; r++) {
        int w4 = r * 128 + t;
        int x  = (w4 >> 3) & 7;
        __stcs(out4 + w4, sm4[w4 ^ x]);
    }
}

// ---------------------------------------------------------------------------
extern "C" void kernel_launch(void* const* d_in, const int* in_sizes, int n_in,
                              void* d_out, int out_size)
{
    const float* jp  = nullptr;
    const float* bp  = nullptr;
    const int*   obs = nullptr;
    for (int i = 0; i < n_in; i++) {
        if (in_sizes[i] == 1)      jp  = (const float*)d_in[i];
        else if (in_sizes[i] == 2) bp  = (const float*)d_in[i];
        else                       obs = (const int*)d_in[i];
    }
    float* out = (float*)d_out;

    fused<<<BATCH, 128>>>(jp, bp, obs, out);
}

// round 5
// speedup vs baseline: 1.0747x; 1.0747x over previous
#include <cuda_runtime.h>
#include <cstddef>

#define LCH   4096
#define BATCH 4096
#define SEG   32
#define NSEG  128

struct Pots { float pd, po, pA0, pA1, pB0, pB1; };

__device__ __forceinline__ Pots make_pots(const float* jp, const float* bp) {
    Pots P;
    float j = jp[0], b0 = bp[0], b1 = bp[1];
    P.pd  = expf( 0.25f * j);
    P.po  = expf(-0.25f * j);
    P.pA0 = expf(-0.5f * b0);  P.pA1 = expf(0.5f * b0);
    P.pB0 = expf(-0.5f * b1);  P.pB1 = expf(0.5f * b1);
    return P;
}

// (max,*) 2x2 matrix product: C = A x B.  layout x=m00 y=m01 z=m10 w=m11
__device__ __forceinline__ float4 mm(float4 A, float4 B) {
    return make_float4(
        fmaxf(A.x * B.x, A.y * B.z), fmaxf(A.x * B.y, A.y * B.w),
        fmaxf(A.z * B.x, A.w * B.z), fmaxf(A.z * B.y, A.w * B.w));
}

__device__ __forceinline__ float4 shflup4(float4 v, int d) {
    v.x = __shfl_up_sync(0xffffffffu, v.x, d);
    v.y = __shfl_up_sync(0xffffffffu, v.y, d);
    v.z = __shfl_up_sync(0xffffffffu, v.z, d);
    v.w = __shfl_up_sync(0xffffffffu, v.w, d);
    return v;
}
__device__ __forceinline__ float4 shfldn4(float4 v, int d) {
    v.x = __shfl_down_sync(0xffffffffu, v.x, d);
    v.y = __shfl_down_sync(0xffffffffu, v.y, d);
    v.z = __shfl_down_sync(0xffffffffu, v.z, d);
    v.w = __shfl_down_sync(0xffffffffu, v.w, d);
    return v;
}

// ---------------------------------------------------------------------------
// One block per row. Segment transfer matrices -> block (max,*) matrix scan
// -> backward checkpoint sweep (checkpoints in smem) -> forward belief sweep
// with local recompute -> coalesced store.
// ---------------------------------------------------------------------------
__global__ void __launch_bounds__(128, 5)
fused(const float* __restrict__ jp, const float* __restrict__ bp,
      const int* __restrict__ obs, float* __restrict__ out)
{
    const int t = threadIdx.x, b = blockIdx.x;
    const int lane = t & 31, warp = t >> 5;

    __shared__ unsigned char smNib[1024];
    __shared__ float4 lutP[16], lutQ[16];
    __shared__ float4 wTotP[4], wTotQ[4];
    __shared__ float2 smCk[8 * 128];        // 8 KB backward checkpoints
    __shared__ float  smo[2 * LCH];         // 32 KB output stage
    float4* sm4 = reinterpret_cast<float4*>(smo);

    const Pots pt = make_pots(jp, bp);

    // ---- obs -> nibbles (coalesced int4 loads) ----
    const int4* row4 = reinterpret_cast<const int4*>(obs + (size_t)b * LCH);
#pragma unroll
    for (int q = 0; q < 8; q++) {
        int  eq = q * 128 + t;
        int4 v  = row4[eq];
        unsigned nib = (v.x & 1) | ((v.y & 1) << 1) | ((v.z & 1) << 2) | ((v.w & 1) << 3);
        smNib[eq] = (unsigned char)nib;
    }

    // ---- 4-bit LUTs of 4-step transfer matrices ----
    if (t < 16) {
        float p00 = 1.f, p01 = 0.f, p10 = 0.f, p11 = 1.f;
        float q00 = 1.f, q01 = 0.f, q10 = 0.f, q11 = 1.f;
#pragma unroll
        for (int i = 0; i < 4; i++) {
            int   o  = (t >> i) & 1;
            float f0 = o ? pt.pB0 : pt.pA0;
            float f1 = o ? pt.pB1 : pt.pA1;
            float x0 = f0 * p00, x1 = f1 * p10, y0 = f0 * p01, y1 = f1 * p11;
            p00 = fmaxf(x0 * pt.pd, x1 * pt.po); p10 = fmaxf(x0 * pt.po, x1 * pt.pd);
            p01 = fmaxf(y0 * pt.pd, y1 * pt.po); p11 = fmaxf(y0 * pt.po, y1 * pt.pd);
            float a = f0 * fmaxf(q00 * pt.pd, q01 * pt.po);
            float c = f1 * fmaxf(q00 * pt.po, q01 * pt.pd);
            float d = f0 * fmaxf(q10 * pt.pd, q11 * pt.po);
            float e = f1 * fmaxf(q10 * pt.po, q11 * pt.pd);
            q00 = a; q01 = c; q10 = d; q11 = e;
        }
        lutP[t] = make_float4(p00, p01, p10, p11);
        lutQ[t] = make_float4(q00, q01, q10, q11);
    }
    __syncthreads();

    // ---- assemble 32-bit mask for segment t ----
    uint2 nb = reinterpret_cast<const uint2*>(smNib)[t];
    unsigned lo   = nb.x | (nb.x >> 4);
    unsigned lo16 = (lo & 0xFFu) | ((lo >> 8) & 0xFF00u);
    unsigned hi   = nb.y | (nb.y >> 4);
    unsigned hi16 = (hi & 0xFFu) | ((hi >> 8) & 0xFF00u);
    const unsigned bits = lo16 | (hi16 << 16);

    // ---- segment transfer matrices via LUT chains ----
    float4 P = lutP[bits & 15];
    float4 Q = lutQ[bits & 15];
#pragma unroll
    for (int c = 1; c < 8; c++) {
        unsigned m = (bits >> (4 * c)) & 15u;
        P = mm(lutP[m], P);
        Q = mm(Q, lutQ[m]);
    }

    // ---- block scan: forward prefix of P, backward suffix of Q ----
    float4 sp = P;
#pragma unroll
    for (int d = 1; d < 32; d <<= 1) {
        float4 o = shflup4(sp, d);
        if (lane >= d) sp = mm(sp, o);
    }
    if (lane == 31) wTotP[warp] = sp;

    float4 sq = Q;
#pragma unroll
    for (int d = 1; d < 32; d <<= 1) {
        float4 o = shfldn4(sq, d);
        if (lane + d < 32) sq = mm(sq, o);
    }
    if (lane == 0) wTotQ[warp] = sq;
    __syncthreads();

    float4 prefP = make_float4(1.f, 0.f, 0.f, 1.f);
#pragma unroll
    for (int k = 2; k >= 0; k--)
        if (warp > k) prefP = mm(prefP, wTotP[k]);

    float4 sufQ = make_float4(1.f, 0.f, 0.f, 1.f);
#pragma unroll
    for (int k = 1; k < 4; k++)
        if (warp < k) sufQ = mm(sufQ, wTotQ[k]);

    float4 exP = shflup4(sp, 1);
    if (lane == 0) exP = make_float4(1.f, 0.f, 0.f, 1.f);
    exP = mm(exP, prefP);
    float f0 = fmaxf(exP.x, exP.y), f1 = fmaxf(exP.z, exP.w);  // fwd msg at seg start

    float4 exQ = shfldn4(sq, 1);
    if (lane == 31) exQ = make_float4(1.f, 0.f, 0.f, 1.f);
    exQ = mm(exQ, sufQ);
    float g0 = fmaxf(exQ.x, exQ.y), g1 = fmaxf(exQ.z, exQ.w);  // bwd msg at seg end

    // ---- backward checkpoint sweep: b at each group-of-4 end -> smem ----
    {
        float bk0 = g0, bk1 = g1;          // b at position 31
#pragma unroll
        for (int gg = 7; gg >= 0; gg--) {
            smCk[gg * 128 + t] = make_float2(bk0, bk1);   // b at pos gg*4+3
#pragma unroll
            for (int u = 3; u >= 0; u--) {
                int   i  = gg * 4 + u;
                int   o  = (bits >> i) & 1;
                float p0 = o ? pt.pB0 : pt.pA0;
                float p1 = o ? pt.pB1 : pt.pA1;
                float y0 = p0 * bk0, y1 = p1 * bk1;
                bk0 = fmaxf(y0 * pt.pd, y1 * pt.po);
                bk1 = fmaxf(y0 * pt.po, y1 * pt.pd);
            }
        }
    }

    // ---- forward belief sweep (recompute b within each group) ----
    const int xr = t & 7;
#pragma unroll
    for (int gg = 0; gg < 8; gg++) {
        float2 ck = smCk[gg * 128 + t];
        float b0[4], b1[4];
        b0[3] = ck.x; b1[3] = ck.y;
#pragma unroll
        for (int u = 3; u >= 1; u--) {
            int   i  = gg * 4 + u;
            int   o  = (bits >> i) & 1;
            float p0 = o ? pt.pB0 : pt.pA0;
            float p1 = o ? pt.pB1 : pt.pA1;
            float y0 = p0 * b0[u], y1 = p1 * b1[u];
            b0[u - 1] = fmaxf(y0 * pt.pd, y1 * pt.po);
            b1[u - 1] = fmaxf(y0 * pt.po, y1 * pt.pd);
        }
        float v0[4], v1[4];
#pragma unroll
        for (int u = 0; u < 4; u++) {
            int   i  = gg * 4 + u;
            int   o  = (bits >> i) & 1;
            float p0 = o ? pt.pB0 : pt.pA0;
            float p1 = o ? pt.pB1 : pt.pA1;
            float x0 = p0 * f0, x1 = p1 * f1;
            v0[u] = x0 * b0[u];
            v1[u] = x1 * b1[u];
            f0 = fmaxf(x0 * pt.pd, x1 * pt.po);
            f1 = fmaxf(x0 * pt.po, x1 * pt.pd);
        }
        sm4[(t * 8 + gg) ^ xr]        = make_float4(v0[0], v0[1], v0[2], v0[3]);
        sm4[(1024 + t * 8 + gg) ^ xr] = make_float4(v1[0], v1[1], v1[2], v1[3]);
    }
    __syncthreads();

    // ---- cooperative fully-coalesced store: out[b][k][t] ----
    float4* out4 = reinterpret_cast<float4*>(out) + (size_t)b * 2048;
#pragma unroll
    for (int r = 0; r < 16; r++) {
        int w4 = r * 128 + t;
        int x  = (w4 >> 3) & 7;
        out4[w4] = sm4[w4 ^ x];
    }
}

// ---------------------------------------------------------------------------
extern "C" void kernel_launch(void* const* d_in, const int* in_sizes, int n_in,
                              void* d_out, int out_size)
{
    const float* jp  = nullptr;
    const float* bp  = nullptr;
    const int*   obs = nullptr;
    for (int i = 0; i < n_in; i++) {
        if (in_sizes[i] == 1)      jp  = (const float*)d_in[i];
        else if (in_sizes[i] == 2) bp  = (const float*)d_in[i];
        else                       obs = (const int*)d_in[i];
    }
    float* out = (float*)d_out;

    fused<<<BATCH, 128>>>(jp, bp, obs, out);
}